// round 13
// baseline (speedup 1.0000x reference)
#include <cuda_runtime.h>
#include <cstdint>

// Problem: B=8, C=16, H=W=64, O=32, K=3, S=1, P=1, G=8, D=144, Kdim=1152
// basis(v,g) = exp(-((v-grid_g)/h)^2); 127*basis = exp2(-u^2 + log2(127)),
// u = v*C1 + C2[g]
#define C1F     2.1019642153762872f
#define LOG2127 6.988684686772166f

__device__ __constant__ float C2F[8] = {
     4.2039284307525744f,  3.0028060219661250f,  1.8016836131796750f,  0.6005612043932250f,
    -0.6005612043932250f, -1.8016836131796750f, -3.0028060219661250f, -4.2039284307525744f
};

// Device scratch (no allocation allowed)
__device__ __align__(16) float g_Wsum[36864];              // fp32 Wsum
__device__ float g_pmax[128];                              // per-CTA partial max|Wsum|
__device__ float g_ssc[32];                                // per-o scale m/127^2
__device__ __align__(16) unsigned char g_Wfrag8[73728];    // s8 2-digit B fragments
__device__ __align__(16) float2 g_part[32 * 128];          // per-(o, cta) sum/sumsq
__device__ unsigned g_barC = 0;                            // monotone barrier counter

// ---------------------------------------------------------------------------
// helpers
// ---------------------------------------------------------------------------
__device__ __forceinline__ float ex2f(float m) {
    float r; asm("ex2.approx.f32 %0, %1;" : "=f"(r) : "f"(m)); return r;
}
__device__ __forceinline__ uint32_t smem_u32(const void* p) {
    uint32_t a;
    asm("{ .reg .u64 t; cvta.to.shared.u64 t, %1; cvt.u32.u64 %0, t; }" : "=r"(a) : "l"(p));
    return a;
}
__device__ __forceinline__ void lds64(uint32_t a, uint32_t& h, uint32_t& l) {
    asm("ld.shared.v2.b32 {%0,%1}, [%2];" : "=r"(h), "=r"(l) : "r"(a));
}
__device__ __forceinline__ uint4 lds128(uint32_t a) {
    uint4 v;
    asm("ld.shared.v4.b32 {%0,%1,%2,%3}, [%4];"
        : "=r"(v.x), "=r"(v.y), "=r"(v.z), "=r"(v.w) : "r"(a));
    return v;
}
// s8 mma: D[16,8] s32 += A[16,32] s8 x B[32,8] s8
__device__ __forceinline__ void mmai(int* c, const uint32_t* a, uint32_t b0, uint32_t b1) {
    asm volatile(
        "mma.sync.aligned.m16n8k32.row.col.s32.s8.s8.s32 "
        "{%0,%1,%2,%3}, {%4,%5,%6,%7}, {%8,%9}, {%0,%1,%2,%3};"
        : "+r"(c[0]), "+r"(c[1]), "+r"(c[2]), "+r"(c[3])
        : "r"(a[0]), "r"(a[1]), "r"(a[2]), "r"(a[3]), "r"(b0), "r"(b1));
}

// Grid barrier over exactly 128 co-resident CTAs. Monotone counter (graph-safe).
__device__ __forceinline__ void grid_barrier(unsigned* ctr) {
    __threadfence();
    __syncthreads();
    if (threadIdx.x == 0) {
        unsigned prev = atomicAdd(ctr, 1u);
        unsigned target = ((prev >> 7) + 1u) << 7;
        unsigned v;
        do {
            asm volatile("ld.acquire.gpu.global.u32 %0, [%1];" : "=r"(v) : "l"(ctr));
        } while ((int)(v - target) < 0);
    }
    __syncthreads();
}

// ---------------------------------------------------------------------------
// Kernel 1: Wsum (fp32) + per-CTA max. 128 CTAs x 288 thr, no smem -> high occ.
// cta = o*4 + quarter; thread handles k = quarter*288 + tid.
// ---------------------------------------------------------------------------
__global__ void __launch_bounds__(288) wsum_max(const float* __restrict__ W) {
    __shared__ float wmax[9];
    const int cta = blockIdx.x;
    const int o   = cta >> 2;
    const int k   = (cta & 3) * 288 + threadIdx.x;
    const float* p = W + (size_t)o * 165888 + k;

    float a[16];
#pragma unroll
    for (int i = 0; i < 16; ++i) a[i] = 0.f;
#pragma unroll
    for (int d = 0; d < 144; d += 16)
#pragma unroll
        for (int i = 0; i < 16; ++i)
            a[i] += p[(d + i) * 1152];
#pragma unroll
    for (int off = 8; off; off >>= 1)
#pragma unroll
        for (int i = 0; i < 8; ++i)
            if (i < off) a[i] += a[i + off];
    float s = a[0];
    g_Wsum[o * 1152 + k] = s;

    float lm = fabsf(s);
#pragma unroll
    for (int off = 16; off; off >>= 1)
        lm = fmaxf(lm, __shfl_xor_sync(0xFFFFFFFFu, lm, off));
    if ((threadIdx.x & 31) == 0) wmax[threadIdx.x >> 5] = lm;
    __syncthreads();
    if (threadIdx.x == 0) {
        float m = wmax[0];
#pragma unroll
        for (int i = 1; i < 9; ++i) m = fmaxf(m, wmax[i]);
        g_pmax[cta] = fmaxf(m, 1e-30f);
    }
}

// ---------------------------------------------------------------------------
// Kernel 2: quantize Wsum -> s8 2-digit fragments + per-o scales.
// ---------------------------------------------------------------------------
__global__ void __launch_bounds__(288) quant_pack() {
    const int cta = blockIdx.x;
    const int o   = cta >> 2;
    const int k   = (cta & 3) * 288 + threadIdx.x;

    const float* pm = g_pmax + o * 4;
    float m = fmaxf(fmaxf(pm[0], pm[1]), fmaxf(pm[2], pm[3]));
    float s = g_Wsum[o * 1152 + k];
    float qf = s * (127.f / m);
    int ih = __float2int_rn(qf);
    float hf = (float)ih;
    int il = __float2int_rn((qf - hf) * 256.f);
    il = min(il, 127);
    int kc = k >> 5, kl = k & 31;
    int base = kc * 2048 + (o >> 3) * 512
             + ((o & 7) * 4 + ((kl & 15) >> 2)) * 16
             + ((kl >> 4) << 2) + (kl & 3);
    ((signed char*)g_Wfrag8)[base]     = (signed char)ih;
    ((signed char*)g_Wfrag8)[base + 8] = (signed char)il;

    if (cta == 0 && threadIdx.x < 32) {
        const float* pp = g_pmax + threadIdx.x * 4;
        float mm = fmaxf(fmaxf(pp[0], pp[1]), fmaxf(pp[2], pp[3]));
        g_ssc[threadIdx.x] = mm * (1.f / 16129.f);     // m / 127^2
    }
}

// ---------------------------------------------------------------------------
// Kernel 3: fused Phi + s8 mma conv + BN. 128 CTAs x 512 thr, 1 CTA/SM.
// Phi int8: per x-element 16B = [h(g0-3) | l(g0-3) | h(g4-7) | l(g4-7)]
// ---------------------------------------------------------------------------
#define PHI_R8   1056                   // 66 cols * 16 B
#define PHI_C8   6336                   // 6 rows * PHI_R8
#define OFF_TAB8 101376                 // 16 ch * PHI_C8
#define SM_W     102528                 // OFF_TAB8 + 2*36*16
#define SMEM_TOT (102528 + 73728)       // + W fragment mirror = 176256 B

__global__ void __launch_bounds__(512, 1) kan_fused(
    const float* __restrict__ x,
    const float* __restrict__ gamma, const float* __restrict__ beta,
    float* __restrict__ out)
{
    extern __shared__ char smem[];
    __shared__ float ssc[32];               // per-o scale m/127^2
    __shared__ float sred[8][4][2][2][4];   // [wp][nt][h][S/Q][gp]
    __shared__ float2 bnp[32];

    const uint32_t sb = smem_u32(smem);
    const int tid = threadIdx.x;
    const int cta = blockIdx.x;
    const int b   = cta >> 4;
    const int r0  = (cta & 15) << 2;

    // ---- kick off W-fragment copy to smem early (cp.async, overlaps Phi) ---
    {
        const char* src = (const char*)g_Wfrag8;
#pragma unroll
        for (int i = tid; i < 4608; i += 512) {
            uint32_t d = sb + SM_W + i * 16;
            asm volatile("cp.async.cg.shared.global [%0], [%1], 16;"
                         :: "r"(d), "l"(src + i * 16) : "memory");
        }
        asm volatile("cp.async.commit_group;" ::: "memory");
    }
    if (tid < 32) ssc[tid] = g_ssc[tid];

    // ---------------- Phi tile (int8 2-digit) + schedule table -------------
#pragma unroll 1
    for (int idx = tid; idx < 6336; idx += 512) {
        int c   = idx / 396;
        int rem = idx - c * 396;
        int r   = rem / 66;
        int col = rem - r * 66;
        int y  = r0 - 1 + r;
        int xx = col - 1;
        float v = 0.f;
        if ((unsigned)y < 64u && (unsigned)xx < 64u)
            v = x[(((b * 16 + c) << 6) + y) * 64 + xx];
        uint32_t hw0 = 0, lw0 = 0, hw1 = 0, lw1 = 0;
#pragma unroll
        for (int g = 0; g < 8; ++g) {
            float u = fmaf(v, C1F, C2F[g]);
            float q = ex2f(fmaf(u, -u, LOG2127));      // 127 * basis, in [0,127]
            int ih = __float2int_rn(q);
            float hf = (float)ih;
            int il = __float2int_rn((q - hf) * 256.f);
            il = min(il, 127);
            int sh = (g & 3) << 3;
            if (g < 4) { hw0 |= (uint32_t)ih << sh; lw0 |= ((uint32_t)il & 0xFFu) << sh; }
            else       { hw1 |= (uint32_t)ih << sh; lw1 |= ((uint32_t)il & 0xFFu) << sh; }
        }
        uint32_t a = sb + c * PHI_C8 + r * PHI_R8 + col * 16;
        asm volatile("st.shared.v4.b32 [%0], {%1,%2,%3,%4};"
                     :: "r"(a), "r"(hw0), "r"(lw0), "r"(hw1), "r"(lw1) : "memory");
    }
    // schedule table: [wh][m in 0..36): chunk kc = wh*18 + (m mod 18)
    // entry = 4 words {off(d0), off(d2), off(d1), off(d3)}, d_i = 4kc+i
    if (tid < 72) {
        int whh = (tid >= 36);
        int m   = tid - whh * 36;
        int cj  = m - (m >= 18 ? 18 : 0);
        int kc  = whh * 18 + cj;
        uint32_t o4[4];
#pragma unroll
        for (int i = 0; i < 4; ++i) {
            int d = 4 * kc + i;
            int c = d / 9, r9 = d - 9 * c;
            o4[i] = (uint32_t)(c * PHI_C8 + (r9 / 3) * PHI_R8 + (r9 % 3) * 16);
        }
        uint32_t a = sb + OFF_TAB8 + tid * 16;
        asm volatile("st.shared.v4.b32 [%0], {%1,%2,%3,%4};"
                     :: "r"(a), "r"(o4[0]), "r"(o4[2]), "r"(o4[1]), "r"(o4[3]) : "memory");
    }
    asm volatile("cp.async.wait_group 0;" ::: "memory");
    __syncthreads();

    // ---------------- s8 mma mainloop (k-split, staggered) -----------------
    const int lane = tid & 31;
    const int w    = tid >> 5;
    const int wh   = w >> 3;                 // k-half
    const int wp   = w & 7;                  // pixel-tile warp id
    const int prow = wp >> 1;
    const int pc   = (wp & 1) << 5;
    const int qr   = lane >> 2;
    const int gp   = lane & 3;
    const int start = wp * 2 + wh;           // 0..15, SMSP-mates desynced

    const uint32_t abase = sb + (uint32_t)prow * PHI_R8
                         + (uint32_t)(pc + qr) * 16 + (uint32_t)(gp & 1) * 8;
    const uint32_t tb    = sb + OFF_TAB8 + (uint32_t)wh * 576
                         + (uint32_t)start * 16 + (uint32_t)(gp >> 1) * 8;
    const uint32_t swB   = sb + SM_W + (uint32_t)wh * 36864 + (uint32_t)lane * 16;

    int acch[2][4][4], accm[2][4][4];
#pragma unroll
    for (int t = 0; t < 2; ++t)
#pragma unroll
        for (int n = 0; n < 4; ++n)
#pragma unroll
            for (int r = 0; r < 4; ++r) { acch[t][n][r] = 0; accm[t][n][r] = 0; }

    uint32_t Eax, Eay;
    lds64(tb, Eax, Eay);
    int cjr = start;

#pragma unroll 3
    for (int j = 0; j < 18; ++j) {
        // ---- A fragments (h+l pairs), 8 x LDS.64 ----
        uint32_t Ah0[4], Al0[4], Ah1[4], Al1[4];
        {
            uint32_t aA = abase + Eax, aB = abase + Eay;
            lds64(aA,        Ah0[0], Al0[0]);
            lds64(aA + 128,  Ah0[1], Al0[1]);
            lds64(aB,        Ah0[2], Al0[2]);
            lds64(aB + 128,  Ah0[3], Al0[3]);
            lds64(aA + 256,  Ah1[0], Al1[0]);
            lds64(aA + 384,  Ah1[1], Al1[1]);
            lds64(aB + 256,  Ah1[2], Al1[2]);
            lds64(aB + 384,  Ah1[3], Al1[3]);
        }
        // ---- B fragments from smem, 4 x LDS.128 ----
        uint32_t bbase = swB + (uint32_t)cjr * 2048;
        uint4 Bb[4];
#pragma unroll
        for (int nl = 0; nl < 4; ++nl) Bb[nl] = lds128(bbase + nl * 512);

        // table prefetch for next iteration
        lds64(tb + (j + 1) * 16, Eax, Eay);

        // ---- 24 mma: HH -> acc_hi ; LH + HL -> acc_mid ----
#pragma unroll
        for (int nl = 0; nl < 4; ++nl) {
            mmai(acch[0][nl], Ah0, Bb[nl].x, Bb[nl].y);
            mmai(acch[1][nl], Ah1, Bb[nl].x, Bb[nl].y);
        }
#pragma unroll
        for (int nl = 0; nl < 4; ++nl) {
            mmai(accm[0][nl], Al0, Bb[nl].x, Bb[nl].y);
            mmai(accm[1][nl], Al1, Bb[nl].x, Bb[nl].y);
        }
#pragma unroll
        for (int nl = 0; nl < 4; ++nl) {
            mmai(accm[0][nl], Ah0, Bb[nl].z, Bb[nl].w);
            mmai(accm[1][nl], Ah1, Bb[nl].z, Bb[nl].w);
        }

        cjr = (cjr == 17) ? 0 : cjr + 1;
    }

    // ---------------- Merge k-halves exactly (int) through dead Phi smem ---
    __syncthreads();
    if (wh == 1) {
        uint32_t mb = sb + (uint32_t)wp * 8192 + (uint32_t)lane * 16;
#pragma unroll
        for (int t = 0; t < 2; ++t)
#pragma unroll
            for (int nl = 0; nl < 4; ++nl) {
                uint32_t a = mb + (uint32_t)(t * 4 + nl) * 512;
                asm volatile("st.shared.v4.b32 [%0], {%1,%2,%3,%4};"
                             :: "r"(a), "r"(acch[t][nl][0]), "r"(acch[t][nl][1]),
                                "r"(acch[t][nl][2]), "r"(acch[t][nl][3]) : "memory");
                asm volatile("st.shared.v4.b32 [%0], {%1,%2,%3,%4};"
                             :: "r"(a + 4096), "r"(accm[t][nl][0]), "r"(accm[t][nl][1]),
                                "r"(accm[t][nl][2]), "r"(accm[t][nl][3]) : "memory");
            }
    }
    __syncthreads();

    float cf[2][4][4];
    if (wh == 0) {
        uint32_t mb = sb + (uint32_t)wp * 8192 + (uint32_t)lane * 16;
#pragma unroll
        for (int t = 0; t < 2; ++t)
#pragma unroll
            for (int nl = 0; nl < 4; ++nl) {
                uint32_t a = mb + (uint32_t)(t * 4 + nl) * 512;
                int h0, h1, h2, h3, m0, m1, m2, m3;
                asm("ld.shared.v4.b32 {%0,%1,%2,%3}, [%4];"
                    : "=r"(h0), "=r"(h1), "=r"(h2), "=r"(h3) : "r"(a));
                asm("ld.shared.v4.b32 {%0,%1,%2,%3}, [%4];"
                    : "=r"(m0), "=r"(m1), "=r"(m2), "=r"(m3) : "r"(a + 4096));
                int H0 = acch[t][nl][0] + h0, M0 = accm[t][nl][0] + m0;
                int H1 = acch[t][nl][1] + h1, M1 = accm[t][nl][1] + m1;
                int H2 = acch[t][nl][2] + h2, M2 = accm[t][nl][2] + m2;
                int H3 = acch[t][nl][3] + h3, M3 = accm[t][nl][3] + m3;
                float s0 = ssc[nl * 8 + (gp << 1)];
                float s1 = ssc[nl * 8 + (gp << 1) + 1];
                const float i256 = 0.00390625f;
                cf[t][nl][0] = s0 * fmaf((float)M0, i256, (float)H0);
                cf[t][nl][1] = s1 * fmaf((float)M1, i256, (float)H1);
                cf[t][nl][2] = s0 * fmaf((float)M2, i256, (float)H2);
                cf[t][nl][3] = s1 * fmaf((float)M3, i256, (float)H3);
            }
    }

    // ---------------- per-o partial stats (wh==0 warps) --------------------
    if (wh == 0) {
        float S[4][2], Q[4][2];
#pragma unroll
        for (int nl = 0; nl < 4; ++nl)
#pragma unroll
            for (int h = 0; h < 2; ++h) {
                float v0 = cf[0][nl][h],     v1 = cf[0][nl][h + 2];
                float v2 = cf[1][nl][h],     v3 = cf[1][nl][h + 2];
                S[nl][h] = (v0 + v1) + (v2 + v3);
                float q = __fmul_rn(v0, v0);
                q = fmaf(v1, v1, q); q = fmaf(v2, v2, q); q = fmaf(v3, v3, q);
                Q[nl][h] = q;
            }
#pragma unroll
        for (int off = 4; off <= 16; off <<= 1)
#pragma unroll
            for (int nl = 0; nl < 4; ++nl)
#pragma unroll
                for (int h = 0; h < 2; ++h) {
                    S[nl][h] += __shfl_xor_sync(0xFFFFFFFFu, S[nl][h], off);
                    Q[nl][h] += __shfl_xor_sync(0xFFFFFFFFu, Q[nl][h], off);
                }
        if (qr == 0) {
#pragma unroll
            for (int nl = 0; nl < 4; ++nl)
#pragma unroll
                for (int h = 0; h < 2; ++h) {
                    sred[wp][nl][h][0][gp] = S[nl][h];
                    sred[wp][nl][h][1][gp] = Q[nl][h];
                }
        }
    }
    __syncthreads();
    if (tid < 32) {
        int o = tid;
        int nt = o >> 3, rem = o & 7, gpp = rem >> 1, h = rem & 1;
        float Ss = 0.f, Qq = 0.f;
#pragma unroll
        for (int ww = 0; ww < 8; ++ww) {
            Ss += sred[ww][nt][h][0][gpp];
            Qq += sred[ww][nt][h][1][gpp];
        }
        g_part[o * 128 + cta] = make_float2(Ss, Qq);
    }

    grid_barrier(&g_barC);

    // ---------------- BN params (deterministic) + apply + store ------------
    if (tid < 256) {
        int o = tid >> 3, jj = tid & 7;
        float Ss = 0.f, Qq = 0.f;
#pragma unroll
        for (int i = 0; i < 16; ++i) {
            float2 pq = g_part[o * 128 + jj * 16 + i];
            Ss += pq.x; Qq += pq.y;
        }
#pragma unroll
        for (int off = 1; off <= 4; off <<= 1) {
            Ss += __shfl_xor_sync(0xFFFFFFFFu, Ss, off);
            Qq += __shfl_xor_sync(0xFFFFFFFFu, Qq, off);
        }
        if (jj == 0) {
            float mean = Ss * (1.f / 32768.f);
            float var  = Qq * (1.f / 32768.f) - mean * mean;
            float sc = gamma[o] * rsqrtf(var + 1e-5f);
            bnp[o] = make_float2(sc, fmaf(-mean, sc, beta[o]));
        }
    }
    __syncthreads();

    if (wh == 0) {
        float* ob = out + ((size_t)b << 17) + (size_t)(r0 + prow) * 64;
#pragma unroll
        for (int t = 0; t < 2; ++t) {
            int col0 = pc + (t << 4) + qr;
#pragma unroll
            for (int nl = 0; nl < 4; ++nl) {
                int o0 = nl * 8 + (gp << 1);
                float2 n0 = bnp[o0];
                float2 n1 = bnp[o0 + 1];
                float* p0 = ob + ((size_t)o0 << 12);
                p0[col0]            = fmaf(cf[t][nl][0], n0.x, n0.y);
                p0[4096 + col0]     = fmaf(cf[t][nl][1], n1.x, n1.y);
                p0[col0 + 8]        = fmaf(cf[t][nl][2], n0.x, n0.y);
                p0[4096 + col0 + 8] = fmaf(cf[t][nl][3], n1.x, n1.y);
            }
        }
    }
}

// ---------------------------------------------------------------------------
extern "C" void kernel_launch(void* const* d_in, const int* in_sizes, int n_in,
                              void* d_out, int out_size) {
    const float* x     = (const float*)d_in[0];
    const float* W     = (const float*)d_in[1];
    const float* gamma = (const float*)d_in[2];
    const float* beta  = (const float*)d_in[3];
    float* out = (float*)d_out;

    cudaFuncSetAttribute(kan_fused, cudaFuncAttributeMaxDynamicSharedMemorySize, SMEM_TOT);

    wsum_max  <<<128, 288>>>(W);
    quant_pack<<<128, 288>>>();
    kan_fused <<<128, 512, SMEM_TOT>>>(x, gamma, beta, out);
}

// round 14
// speedup vs baseline: 1.0028x; 1.0028x over previous
#include <cuda_runtime.h>
#include <cstdint>

// Problem: B=8, C=16, H=W=64, O=32, K=3, S=1, P=1, G=8, D=144, Kdim=1152
// basis(v,g) = exp(-((v-grid_g)/h)^2); 127*basis = exp2(-u^2 + log2(127)),
// u = v*C1 + C2[g]
#define C1F     2.1019642153762872f
#define LOG2127 6.988684686772166f

__device__ __constant__ float C2F[8] = {
     4.2039284307525744f,  3.0028060219661250f,  1.8016836131796750f,  0.6005612043932250f,
    -0.6005612043932250f, -1.8016836131796750f, -3.0028060219661250f, -4.2039284307525744f
};

// Device scratch (no allocation allowed)
__device__ __align__(16) float4 g_Wpart4[73728];           // 8 d-octant partials (1.18MB)
__device__ float g_ssc[32];                                // per-o scale m/127^2
__device__ __align__(16) unsigned char g_Wfrag8[73728];    // s8 2-digit B fragments
__device__ __align__(16) float2 g_part[32 * 128];          // per-(o, cta) sum/sumsq
__device__ unsigned g_barC = 0;                            // monotone barrier counter

// ---------------------------------------------------------------------------
// helpers
// ---------------------------------------------------------------------------
__device__ __forceinline__ float ex2f(float m) {
    float r; asm("ex2.approx.f32 %0, %1;" : "=f"(r) : "f"(m)); return r;
}
__device__ __forceinline__ uint32_t smem_u32(const void* p) {
    uint32_t a;
    asm("{ .reg .u64 t; cvta.to.shared.u64 t, %1; cvt.u32.u64 %0, t; }" : "=r"(a) : "l"(p));
    return a;
}
__device__ __forceinline__ void lds64(uint32_t a, uint32_t& h, uint32_t& l) {
    asm("ld.shared.v2.b32 {%0,%1}, [%2];" : "=r"(h), "=r"(l) : "r"(a));
}
__device__ __forceinline__ uint4 lds128(uint32_t a) {
    uint4 v;
    asm("ld.shared.v4.b32 {%0,%1,%2,%3}, [%4];"
        : "=r"(v.x), "=r"(v.y), "=r"(v.z), "=r"(v.w) : "r"(a));
    return v;
}
// s8 mma: D[16,8] s32 += A[16,32] s8 x B[32,8] s8
__device__ __forceinline__ void mmai(int* c, const uint32_t* a, uint32_t b0, uint32_t b1) {
    asm volatile(
        "mma.sync.aligned.m16n8k32.row.col.s32.s8.s8.s32 "
        "{%0,%1,%2,%3}, {%4,%5,%6,%7}, {%8,%9}, {%0,%1,%2,%3};"
        : "+r"(c[0]), "+r"(c[1]), "+r"(c[2]), "+r"(c[3])
        : "r"(a[0]), "r"(a[1]), "r"(a[2]), "r"(a[3]), "r"(b0), "r"(b1));
}

// Grid barrier over exactly 128 co-resident CTAs. Monotone counter (graph-safe).
__device__ __forceinline__ void grid_barrier(unsigned* ctr) {
    __threadfence();
    __syncthreads();
    if (threadIdx.x == 0) {
        unsigned prev = atomicAdd(ctr, 1u);
        unsigned target = ((prev >> 7) + 1u) << 7;
        unsigned v;
        do {
            asm volatile("ld.acquire.gpu.global.u32 %0, [%1];" : "=r"(v) : "l"(ctr));
        } while ((int)(v - target) < 0);
    }
    __syncthreads();
}

// ---------------------------------------------------------------------------
// Kernel 1: W partial sums. grid 256 = 32 o x 8 d-octants; block 288.
// Thread t owns float4 k-group t (k = 4t..4t+3); 18 LDG.128 front-batched.
// ---------------------------------------------------------------------------
__global__ void __launch_bounds__(288) wsum_part(const float* __restrict__ W) {
    const int cta = blockIdx.x;
    const int o   = cta >> 3;
    const int dq  = cta & 7;
    const int t   = threadIdx.x;
    const float4* p = (const float4*)(W + (size_t)o * 165888)
                    + (size_t)(dq * 18) * 288 + t;

    float4 v[18];
#pragma unroll
    for (int i = 0; i < 18; ++i) v[i] = p[(size_t)i * 288];

    float sx = 0.f, sy = 0.f, sz = 0.f, sw = 0.f;
#pragma unroll
    for (int i = 0; i < 18; ++i) {
        sx += v[i].x; sy += v[i].y; sz += v[i].z; sw += v[i].w;
    }
    float4 s; s.x = sx; s.y = sy; s.z = sz; s.w = sw;
    g_Wpart4[dq * 9216 + o * 288 + t] = s;
}

// ---------------------------------------------------------------------------
// Kernel 2: combine octant partials, block max per o, quantize to s8 frags.
// grid 32 (one CTA per o), block 576; thread handles k = tid and tid+576.
// ---------------------------------------------------------------------------
__global__ void __launch_bounds__(576) sum_quant() {
    __shared__ float wmax[18];
    __shared__ float mglob;
    const int o   = blockIdx.x;
    const int tid = threadIdx.x;
    const float* wp = (const float*)g_Wpart4;   // scalar view

    float s[2];
#pragma unroll
    for (int h = 0; h < 2; ++h) {
        int k = tid + h * 576;
        float acc = 0.f;
#pragma unroll
        for (int dq = 0; dq < 8; ++dq)
            acc += wp[dq * 36864 + o * 1152 + k];
        s[h] = acc;
    }
    float lm = fmaxf(fabsf(s[0]), fabsf(s[1]));
#pragma unroll
    for (int off = 16; off; off >>= 1)
        lm = fmaxf(lm, __shfl_xor_sync(0xFFFFFFFFu, lm, off));
    if ((tid & 31) == 0) wmax[tid >> 5] = lm;
    __syncthreads();
    if (tid == 0) {
        float m = wmax[0];
#pragma unroll
        for (int i = 1; i < 18; ++i) m = fmaxf(m, wmax[i]);
        m = fmaxf(m, 1e-30f);
        mglob = m;
        g_ssc[o] = m * (1.f / 16129.f);          // m / 127^2
    }
    __syncthreads();

    const float m = mglob;
#pragma unroll
    for (int h = 0; h < 2; ++h) {
        int k = tid + h * 576;
        float qf = s[h] * (127.f / m);
        int ih = __float2int_rn(qf);
        float hf = (float)ih;
        int il = __float2int_rn((qf - hf) * 256.f);
        il = min(il, 127);
        int kc = k >> 5, kl = k & 31;
        int base = kc * 2048 + (o >> 3) * 512
                 + ((o & 7) * 4 + ((kl & 15) >> 2)) * 16
                 + ((kl >> 4) << 2) + (kl & 3);
        ((signed char*)g_Wfrag8)[base]     = (signed char)ih;
        ((signed char*)g_Wfrag8)[base + 8] = (signed char)il;
    }
}

// ---------------------------------------------------------------------------
// Kernel 3: fused Phi + s8 mma conv + BN. 128 CTAs x 512 thr, 1 CTA/SM.
// Phi int8: per x-element 16B = [h(g0-3) | l(g0-3) | h(g4-7) | l(g4-7)]
// ---------------------------------------------------------------------------
#define PHI_R8   1056                   // 66 cols * 16 B
#define PHI_C8   6336                   // 6 rows * PHI_R8
#define OFF_TAB8 101376                 // 16 ch * PHI_C8
#define SM_W     102528                 // OFF_TAB8 + 2*36*16
#define SMEM_TOT (102528 + 73728)       // + W fragment mirror = 176256 B

__global__ void __launch_bounds__(512, 1) kan_fused(
    const float* __restrict__ x,
    const float* __restrict__ gamma, const float* __restrict__ beta,
    float* __restrict__ out)
{
    extern __shared__ char smem[];
    __shared__ float ssc[32];               // per-o scale m/127^2
    __shared__ float sred[8][4][2][2][4];   // [wp][nt][h][S/Q][gp]
    __shared__ float2 bnp[32];

    const uint32_t sb = smem_u32(smem);
    const int tid = threadIdx.x;
    const int cta = blockIdx.x;
    const int b   = cta >> 4;
    const int r0  = (cta & 15) << 2;

    // ---- kick off W-fragment copy to smem early (cp.async, overlaps Phi) ---
    {
        const char* src = (const char*)g_Wfrag8;
#pragma unroll
        for (int i = tid; i < 4608; i += 512) {
            uint32_t d = sb + SM_W + i * 16;
            asm volatile("cp.async.cg.shared.global [%0], [%1], 16;"
                         :: "r"(d), "l"(src + i * 16) : "memory");
        }
        asm volatile("cp.async.commit_group;" ::: "memory");
    }
    if (tid < 32) ssc[tid] = g_ssc[tid];

    // ---------------- Phi tile (int8 2-digit) + schedule table -------------
#pragma unroll 1
    for (int idx = tid; idx < 6336; idx += 512) {
        int c   = idx / 396;
        int rem = idx - c * 396;
        int r   = rem / 66;
        int col = rem - r * 66;
        int y  = r0 - 1 + r;
        int xx = col - 1;
        float v = 0.f;
        if ((unsigned)y < 64u && (unsigned)xx < 64u)
            v = x[(((b * 16 + c) << 6) + y) * 64 + xx];
        uint32_t hw0 = 0, lw0 = 0, hw1 = 0, lw1 = 0;
#pragma unroll
        for (int g = 0; g < 8; ++g) {
            float u = fmaf(v, C1F, C2F[g]);
            float q = ex2f(fmaf(u, -u, LOG2127));      // 127 * basis, in [0,127]
            int ih = __float2int_rn(q);
            float hf = (float)ih;
            int il = __float2int_rn((q - hf) * 256.f);
            il = min(il, 127);
            int sh = (g & 3) << 3;
            if (g < 4) { hw0 |= (uint32_t)ih << sh; lw0 |= ((uint32_t)il & 0xFFu) << sh; }
            else       { hw1 |= (uint32_t)ih << sh; lw1 |= ((uint32_t)il & 0xFFu) << sh; }
        }
        uint32_t a = sb + c * PHI_C8 + r * PHI_R8 + col * 16;
        asm volatile("st.shared.v4.b32 [%0], {%1,%2,%3,%4};"
                     :: "r"(a), "r"(hw0), "r"(lw0), "r"(hw1), "r"(lw1) : "memory");
    }
    // schedule table: [wh][m in 0..36): chunk kc = wh*18 + (m mod 18)
    // entry = 4 words {off(d0), off(d2), off(d1), off(d3)}, d_i = 4kc+i
    if (tid < 72) {
        int whh = (tid >= 36);
        int m   = tid - whh * 36;
        int cj  = m - (m >= 18 ? 18 : 0);
        int kc  = whh * 18 + cj;
        uint32_t o4[4];
#pragma unroll
        for (int i = 0; i < 4; ++i) {
            int d = 4 * kc + i;
            int c = d / 9, r9 = d - 9 * c;
            o4[i] = (uint32_t)(c * PHI_C8 + (r9 / 3) * PHI_R8 + (r9 % 3) * 16);
        }
        uint32_t a = sb + OFF_TAB8 + tid * 16;
        asm volatile("st.shared.v4.b32 [%0], {%1,%2,%3,%4};"
                     :: "r"(a), "r"(o4[0]), "r"(o4[2]), "r"(o4[1]), "r"(o4[3]) : "memory");
    }
    asm volatile("cp.async.wait_group 0;" ::: "memory");
    __syncthreads();

    // ---------------- s8 mma mainloop (k-split, staggered) -----------------
    const int lane = tid & 31;
    const int w    = tid >> 5;
    const int wh   = w >> 3;                 // k-half
    const int wp   = w & 7;                  // pixel-tile warp id
    const int prow = wp >> 1;
    const int pc   = (wp & 1) << 5;
    const int qr   = lane >> 2;
    const int gp   = lane & 3;
    const int start = wp * 2 + wh;           // 0..15, SMSP-mates desynced

    const uint32_t abase = sb + (uint32_t)prow * PHI_R8
                         + (uint32_t)(pc + qr) * 16 + (uint32_t)(gp & 1) * 8;
    const uint32_t tb    = sb + OFF_TAB8 + (uint32_t)wh * 576
                         + (uint32_t)start * 16 + (uint32_t)(gp >> 1) * 8;
    const uint32_t swB   = sb + SM_W + (uint32_t)wh * 36864 + (uint32_t)lane * 16;

    int acch[2][4][4], accm[2][4][4];
#pragma unroll
    for (int t = 0; t < 2; ++t)
#pragma unroll
        for (int n = 0; n < 4; ++n)
#pragma unroll
            for (int r = 0; r < 4; ++r) { acch[t][n][r] = 0; accm[t][n][r] = 0; }

    uint32_t Eax, Eay;
    lds64(tb, Eax, Eay);
    int cjr = start;

#pragma unroll 3
    for (int j = 0; j < 18; ++j) {
        // ---- A fragments (h+l pairs), 8 x LDS.64 ----
        uint32_t Ah0[4], Al0[4], Ah1[4], Al1[4];
        {
            uint32_t aA = abase + Eax, aB = abase + Eay;
            lds64(aA,        Ah0[0], Al0[0]);
            lds64(aA + 128,  Ah0[1], Al0[1]);
            lds64(aB,        Ah0[2], Al0[2]);
            lds64(aB + 128,  Ah0[3], Al0[3]);
            lds64(aA + 256,  Ah1[0], Al1[0]);
            lds64(aA + 384,  Ah1[1], Al1[1]);
            lds64(aB + 256,  Ah1[2], Al1[2]);
            lds64(aB + 384,  Ah1[3], Al1[3]);
        }
        // ---- B fragments from smem, 4 x LDS.128 ----
        uint32_t bbase = swB + (uint32_t)cjr * 2048;
        uint4 Bb[4];
#pragma unroll
        for (int nl = 0; nl < 4; ++nl) Bb[nl] = lds128(bbase + nl * 512);

        // table prefetch for next iteration
        lds64(tb + (j + 1) * 16, Eax, Eay);

        // ---- 24 mma: HH -> acc_hi ; LH + HL -> acc_mid ----
#pragma unroll
        for (int nl = 0; nl < 4; ++nl) {
            mmai(acch[0][nl], Ah0, Bb[nl].x, Bb[nl].y);
            mmai(acch[1][nl], Ah1, Bb[nl].x, Bb[nl].y);
        }
#pragma unroll
        for (int nl = 0; nl < 4; ++nl) {
            mmai(accm[0][nl], Al0, Bb[nl].x, Bb[nl].y);
            mmai(accm[1][nl], Al1, Bb[nl].x, Bb[nl].y);
        }
#pragma unroll
        for (int nl = 0; nl < 4; ++nl) {
            mmai(accm[0][nl], Ah0, Bb[nl].z, Bb[nl].w);
            mmai(accm[1][nl], Ah1, Bb[nl].z, Bb[nl].w);
        }

        cjr = (cjr == 17) ? 0 : cjr + 1;
    }

    // ---------------- Merge k-halves exactly (int) through dead Phi smem ---
    __syncthreads();
    if (wh == 1) {
        uint32_t mb = sb + (uint32_t)wp * 8192 + (uint32_t)lane * 16;
#pragma unroll
        for (int t = 0; t < 2; ++t)
#pragma unroll
            for (int nl = 0; nl < 4; ++nl) {
                uint32_t a = mb + (uint32_t)(t * 4 + nl) * 512;
                asm volatile("st.shared.v4.b32 [%0], {%1,%2,%3,%4};"
                             :: "r"(a), "r"(acch[t][nl][0]), "r"(acch[t][nl][1]),
                                "r"(acch[t][nl][2]), "r"(acch[t][nl][3]) : "memory");
                asm volatile("st.shared.v4.b32 [%0], {%1,%2,%3,%4};"
                             :: "r"(a + 4096), "r"(accm[t][nl][0]), "r"(accm[t][nl][1]),
                                "r"(accm[t][nl][2]), "r"(accm[t][nl][3]) : "memory");
            }
    }
    __syncthreads();

    float cf[2][4][4];
    if (wh == 0) {
        uint32_t mb = sb + (uint32_t)wp * 8192 + (uint32_t)lane * 16;
#pragma unroll
        for (int t = 0; t < 2; ++t)
#pragma unroll
            for (int nl = 0; nl < 4; ++nl) {
                uint32_t a = mb + (uint32_t)(t * 4 + nl) * 512;
                int h0, h1, h2, h3, m0, m1, m2, m3;
                asm("ld.shared.v4.b32 {%0,%1,%2,%3}, [%4];"
                    : "=r"(h0), "=r"(h1), "=r"(h2), "=r"(h3) : "r"(a));
                asm("ld.shared.v4.b32 {%0,%1,%2,%3}, [%4];"
                    : "=r"(m0), "=r"(m1), "=r"(m2), "=r"(m3) : "r"(a + 4096));
                int H0 = acch[t][nl][0] + h0, M0 = accm[t][nl][0] + m0;
                int H1 = acch[t][nl][1] + h1, M1 = accm[t][nl][1] + m1;
                int H2 = acch[t][nl][2] + h2, M2 = accm[t][nl][2] + m2;
                int H3 = acch[t][nl][3] + h3, M3 = accm[t][nl][3] + m3;
                float s0 = ssc[nl * 8 + (gp << 1)];
                float s1 = ssc[nl * 8 + (gp << 1) + 1];
                const float i256 = 0.00390625f;
                cf[t][nl][0] = s0 * fmaf((float)M0, i256, (float)H0);
                cf[t][nl][1] = s1 * fmaf((float)M1, i256, (float)H1);
                cf[t][nl][2] = s0 * fmaf((float)M2, i256, (float)H2);
                cf[t][nl][3] = s1 * fmaf((float)M3, i256, (float)H3);
            }
    }

    // ---------------- per-o partial stats (wh==0 warps) --------------------
    if (wh == 0) {
        float S[4][2], Q[4][2];
#pragma unroll
        for (int nl = 0; nl < 4; ++nl)
#pragma unroll
            for (int h = 0; h < 2; ++h) {
                float v0 = cf[0][nl][h],     v1 = cf[0][nl][h + 2];
                float v2 = cf[1][nl][h],     v3 = cf[1][nl][h + 2];
                S[nl][h] = (v0 + v1) + (v2 + v3);
                float q = __fmul_rn(v0, v0);
                q = fmaf(v1, v1, q); q = fmaf(v2, v2, q); q = fmaf(v3, v3, q);
                Q[nl][h] = q;
            }
#pragma unroll
        for (int off = 4; off <= 16; off <<= 1)
#pragma unroll
            for (int nl = 0; nl < 4; ++nl)
#pragma unroll
                for (int h = 0; h < 2; ++h) {
                    S[nl][h] += __shfl_xor_sync(0xFFFFFFFFu, S[nl][h], off);
                    Q[nl][h] += __shfl_xor_sync(0xFFFFFFFFu, Q[nl][h], off);
                }
        if (qr == 0) {
#pragma unroll
            for (int nl = 0; nl < 4; ++nl)
#pragma unroll
                for (int h = 0; h < 2; ++h) {
                    sred[wp][nl][h][0][gp] = S[nl][h];
                    sred[wp][nl][h][1][gp] = Q[nl][h];
                }
        }
    }
    __syncthreads();
    if (tid < 32) {
        int o = tid;
        int nt = o >> 3, rem = o & 7, gpp = rem >> 1, h = rem & 1;
        float Ss = 0.f, Qq = 0.f;
#pragma unroll
        for (int ww = 0; ww < 8; ++ww) {
            Ss += sred[ww][nt][h][0][gpp];
            Qq += sred[ww][nt][h][1][gpp];
        }
        g_part[o * 128 + cta] = make_float2(Ss, Qq);
    }

    grid_barrier(&g_barC);

    // ---------------- BN params (deterministic) + apply + store ------------
    if (tid < 256) {
        int o = tid >> 3, jj = tid & 7;
        float Ss = 0.f, Qq = 0.f;
#pragma unroll
        for (int i = 0; i < 16; ++i) {
            float2 pq = g_part[o * 128 + jj * 16 + i];
            Ss += pq.x; Qq += pq.y;
        }
#pragma unroll
        for (int off = 1; off <= 4; off <<= 1) {
            Ss += __shfl_xor_sync(0xFFFFFFFFu, Ss, off);
            Qq += __shfl_xor_sync(0xFFFFFFFFu, Qq, off);
        }
        if (jj == 0) {
            float mean = Ss * (1.f / 32768.f);
            float var  = Qq * (1.f / 32768.f) - mean * mean;
            float sc = gamma[o] * rsqrtf(var + 1e-5f);
            bnp[o] = make_float2(sc, fmaf(-mean, sc, beta[o]));
        }
    }
    __syncthreads();

    if (wh == 0) {
        float* ob = out + ((size_t)b << 17) + (size_t)(r0 + prow) * 64;
#pragma unroll
        for (int t = 0; t < 2; ++t) {
            int col0 = pc + (t << 4) + qr;
#pragma unroll
            for (int nl = 0; nl < 4; ++nl) {
                int o0 = nl * 8 + (gp << 1);
                float2 n0 = bnp[o0];
                float2 n1 = bnp[o0 + 1];
                float* p0 = ob + ((size_t)o0 << 12);
                p0[col0]            = fmaf(cf[t][nl][0], n0.x, n0.y);
                p0[4096 + col0]     = fmaf(cf[t][nl][1], n1.x, n1.y);
                p0[col0 + 8]        = fmaf(cf[t][nl][2], n0.x, n0.y);
                p0[4096 + col0 + 8] = fmaf(cf[t][nl][3], n1.x, n1.y);
            }
        }
    }
}

// ---------------------------------------------------------------------------
extern "C" void kernel_launch(void* const* d_in, const int* in_sizes, int n_in,
                              void* d_out, int out_size) {
    const float* x     = (const float*)d_in[0];
    const float* W     = (const float*)d_in[1];
    const float* gamma = (const float*)d_in[2];
    const float* beta  = (const float*)d_in[3];
    float* out = (float*)d_out;

    cudaFuncSetAttribute(kan_fused, cudaFuncAttributeMaxDynamicSharedMemorySize, SMEM_TOT);

    wsum_part<<<256, 288>>>(W);
    sum_quant<<<32, 576>>>();
    kan_fused<<<128, 512, SMEM_TOT>>>(x, gamma, beta, out);
}

// round 15
// speedup vs baseline: 1.0654x; 1.0625x over previous
#include <cuda_runtime.h>
#include <cstdint>

// Problem: B=8, C=16, H=W=64, O=32, K=3, S=1, P=1, G=8, D=144, Kdim=1152
// basis(v,g) = exp(-((v-grid_g)/h)^2); 127*basis = exp2(-u^2 + log2(127)),
// u = v*C1 + C2[g]
#define C1F     2.1019642153762872f
#define LOG2127 6.988684686772166f

__device__ __constant__ float C2F[8] = {
     4.2039284307525744f,  3.0028060219661250f,  1.8016836131796750f,  0.6005612043932250f,
    -0.6005612043932250f, -1.8016836131796750f, -3.0028060219661250f, -4.2039284307525744f
};

// Device scratch (no allocation allowed)
__device__ __align__(16) float4 g_Wpart4[16 * 9216];       // 16 d-group partials (2.25MB)
__device__ __align__(16) float g_Wsum[36864];              // full fp32 Wsum
__device__ float g_pmax[128];                              // per-(o,kq) partial max|Wsum|
__device__ float g_ssc[32];                                // per-o scale m/127^2
__device__ __align__(16) unsigned char g_Wfrag8[73728];    // s8 2-digit B fragments
__device__ __align__(16) float2 g_part[32 * 128];          // per-(o, cta) sum/sumsq
__device__ unsigned g_barC = 0;                            // monotone barrier counter

// ---------------------------------------------------------------------------
// helpers
// ---------------------------------------------------------------------------
__device__ __forceinline__ float ex2f(float m) {
    float r; asm("ex2.approx.f32 %0, %1;" : "=f"(r) : "f"(m)); return r;
}
__device__ __forceinline__ uint32_t smem_u32(const void* p) {
    uint32_t a;
    asm("{ .reg .u64 t; cvta.to.shared.u64 t, %1; cvt.u32.u64 %0, t; }" : "=r"(a) : "l"(p));
    return a;
}
__device__ __forceinline__ void lds64(uint32_t a, uint32_t& h, uint32_t& l) {
    asm("ld.shared.v2.b32 {%0,%1}, [%2];" : "=r"(h), "=r"(l) : "r"(a));
}
__device__ __forceinline__ uint4 lds128(uint32_t a) {
    uint4 v;
    asm("ld.shared.v4.b32 {%0,%1,%2,%3}, [%4];"
        : "=r"(v.x), "=r"(v.y), "=r"(v.z), "=r"(v.w) : "r"(a));
    return v;
}
// s8 mma: D[16,8] s32 += A[16,32] s8 x B[32,8] s8
__device__ __forceinline__ void mmai(int* c, const uint32_t* a, uint32_t b0, uint32_t b1) {
    asm volatile(
        "mma.sync.aligned.m16n8k32.row.col.s32.s8.s8.s32 "
        "{%0,%1,%2,%3}, {%4,%5,%6,%7}, {%8,%9}, {%0,%1,%2,%3};"
        : "+r"(c[0]), "+r"(c[1]), "+r"(c[2]), "+r"(c[3])
        : "r"(a[0]), "r"(a[1]), "r"(a[2]), "r"(a[3]), "r"(b0), "r"(b1));
}

// Grid barrier over exactly 128 co-resident CTAs. Monotone counter (graph-safe).
__device__ __forceinline__ void grid_barrier(unsigned* ctr) {
    __threadfence();
    __syncthreads();
    if (threadIdx.x == 0) {
        unsigned prev = atomicAdd(ctr, 1u);
        unsigned target = ((prev >> 7) + 1u) << 7;
        unsigned v;
        do {
            asm volatile("ld.acquire.gpu.global.u32 %0, [%1];" : "=r"(v) : "l"(ctr));
        } while ((int)(v - target) < 0);
    }
    __syncthreads();
}

// ---------------------------------------------------------------------------
// Kernel 1: W partial sums. grid 512 = 32 o x 16 d-groups (9 d each); blk 288.
// Thread t owns float4 k-group t; 9 LDG.128 front-batched.
// ---------------------------------------------------------------------------
__global__ void __launch_bounds__(288) wsum_part(const float* __restrict__ W) {
    const int cta = blockIdx.x;
    const int o   = cta >> 4;
    const int dq  = cta & 15;
    const int t   = threadIdx.x;
    const float4* p = (const float4*)(W + (size_t)o * 165888)
                    + (size_t)(dq * 9) * 288 + t;

    float4 v[9];
#pragma unroll
    for (int i = 0; i < 9; ++i) v[i] = p[(size_t)i * 288];

    float sx = 0.f, sy = 0.f, sz = 0.f, sw = 0.f;
#pragma unroll
    for (int i = 0; i < 9; ++i) {
        sx += v[i].x; sy += v[i].y; sz += v[i].z; sw += v[i].w;
    }
    float4 s; s.x = sx; s.y = sy; s.z = sz; s.w = sw;
    g_Wpart4[dq * 9216 + o * 288 + t] = s;
}

// ---------------------------------------------------------------------------
// Kernel 2a: combine 16 d-group partials -> g_Wsum; per-(o,kq) max -> g_pmax.
// grid 128 = 32 o x 4 k-quarters; block 288.
// ---------------------------------------------------------------------------
__global__ void __launch_bounds__(288) wsum_comb() {
    __shared__ float wmax[9];
    const int cta = blockIdx.x;
    const int o   = cta >> 2;
    const int k   = (cta & 3) * 288 + threadIdx.x;
    const float* wp = (const float*)g_Wpart4;   // scalar view

    float acc = 0.f;
#pragma unroll
    for (int dq = 0; dq < 16; ++dq)
        acc += wp[dq * 36864 + o * 1152 + k];
    g_Wsum[o * 1152 + k] = acc;

    float lm = fabsf(acc);
#pragma unroll
    for (int off = 16; off; off >>= 1)
        lm = fmaxf(lm, __shfl_xor_sync(0xFFFFFFFFu, lm, off));
    if ((threadIdx.x & 31) == 0) wmax[threadIdx.x >> 5] = lm;
    __syncthreads();
    if (threadIdx.x == 0) {
        float m = wmax[0];
#pragma unroll
        for (int i = 1; i < 9; ++i) m = fmaxf(m, wmax[i]);
        g_pmax[cta] = fmaxf(m, 1e-30f);
    }
}

// ---------------------------------------------------------------------------
// Kernel 2b: quantize Wsum -> s8 2-digit fragments + per-o scales. grid 128.
// ---------------------------------------------------------------------------
__global__ void __launch_bounds__(288) quant_pack() {
    const int cta = blockIdx.x;
    const int o   = cta >> 2;
    const int k   = (cta & 3) * 288 + threadIdx.x;

    const float* pm = g_pmax + o * 4;
    float m = fmaxf(fmaxf(pm[0], pm[1]), fmaxf(pm[2], pm[3]));
    float s = g_Wsum[o * 1152 + k];
    float qf = s * (127.f / m);
    int ih = __float2int_rn(qf);
    float hf = (float)ih;
    int il = __float2int_rn((qf - hf) * 256.f);
    il = min(il, 127);
    int kc = k >> 5, kl = k & 31;
    int base = kc * 2048 + (o >> 3) * 512
             + ((o & 7) * 4 + ((kl & 15) >> 2)) * 16
             + ((kl >> 4) << 2) + (kl & 3);
    ((signed char*)g_Wfrag8)[base]     = (signed char)ih;
    ((signed char*)g_Wfrag8)[base + 8] = (signed char)il;

    if (cta == 0 && threadIdx.x < 32) {
        const float* pp = g_pmax + threadIdx.x * 4;
        float mm = fmaxf(fmaxf(pp[0], pp[1]), fmaxf(pp[2], pp[3]));
        g_ssc[threadIdx.x] = mm * (1.f / 16129.f);     // m / 127^2
    }
}

// ---------------------------------------------------------------------------
// Kernel 3: fused Phi + s8 mma conv + BN. 128 CTAs x 512 thr, 1 CTA/SM.
// Phi int8: per x-element 16B = [h(g0-3) | l(g0-3) | h(g4-7) | l(g4-7)]
// ---------------------------------------------------------------------------
#define PHI_R8   1056                   // 66 cols * 16 B
#define PHI_C8   6336                   // 6 rows * PHI_R8
#define OFF_TAB8 101376                 // 16 ch * PHI_C8
#define SM_W     102528                 // OFF_TAB8 + 2*36*16
#define SMEM_TOT (102528 + 73728)       // + W fragment mirror = 176256 B

// quantize one x value -> 4 packed words {h0-3, l0-3, h4-7, l4-7}
__device__ __forceinline__ void phi_quant(float v, uint32_t& hw0, uint32_t& lw0,
                                          uint32_t& hw1, uint32_t& lw1) {
    hw0 = lw0 = hw1 = lw1 = 0u;
#pragma unroll
    for (int g = 0; g < 8; ++g) {
        float u = fmaf(v, C1F, C2F[g]);
        float q = ex2f(fmaf(u, -u, LOG2127));          // 127 * basis, in [0,127]
        int ih = __float2int_rn(q);
        float hf = (float)ih;
        int il = __float2int_rn((q - hf) * 256.f);
        il = min(il, 127);
        int sh = (g & 3) << 3;
        if (g < 4) { hw0 |= (uint32_t)ih << sh; lw0 |= ((uint32_t)il & 0xFFu) << sh; }
        else       { hw1 |= (uint32_t)ih << sh; lw1 |= ((uint32_t)il & 0xFFu) << sh; }
    }
}

__global__ void __launch_bounds__(512, 1) kan_fused(
    const float* __restrict__ x,
    const float* __restrict__ gamma, const float* __restrict__ beta,
    float* __restrict__ out)
{
    extern __shared__ char smem[];
    __shared__ float ssc[32];               // per-o scale m/127^2
    __shared__ float sred[8][4][2][2][4];   // [wp][nt][h][S/Q][gp]
    __shared__ float2 bnp[32];

    const uint32_t sb = smem_u32(smem);
    const int tid = threadIdx.x;
    const int cta = blockIdx.x;
    const int b   = cta >> 4;
    const int r0  = (cta & 15) << 2;

    // ---- kick off W-fragment copy to smem early (cp.async, overlaps Phi) ---
    {
        const char* src = (const char*)g_Wfrag8;
#pragma unroll
        for (int i = tid; i < 4608; i += 512) {
            uint32_t d = sb + SM_W + i * 16;
            asm volatile("cp.async.cg.shared.global [%0], [%1], 16;"
                         :: "r"(d), "l"(src + i * 16) : "memory");
        }
        asm volatile("cp.async.commit_group;" ::: "memory");
    }
    if (tid < 32) ssc[tid] = g_ssc[tid];

    // ---------------- Phi tile: front-batched x loads (MLP=12), then quant --
    {
        float xv[12];
        uint32_t sad[12];
#pragma unroll
        for (int i = 0; i < 12; ++i) {
            int idx = tid + i * 512;                // max 6143 < 6336
            int c   = idx / 396;
            int rem = idx - c * 396;
            int r   = rem / 66;
            int col = rem - r * 66;
            int y  = r0 - 1 + r;
            int xx = col - 1;
            float v = 0.f;
            if ((unsigned)y < 64u && (unsigned)xx < 64u)
                v = x[(((b * 16 + c) << 6) + y) * 64 + xx];
            xv[i]  = v;
            sad[i] = sb + c * PHI_C8 + r * PHI_R8 + col * 16;
        }
#pragma unroll
        for (int i = 0; i < 12; ++i) {
            uint32_t hw0, lw0, hw1, lw1;
            phi_quant(xv[i], hw0, lw0, hw1, lw1);
            asm volatile("st.shared.v4.b32 [%0], {%1,%2,%3,%4};"
                         :: "r"(sad[i]), "r"(hw0), "r"(lw0), "r"(hw1), "r"(lw1) : "memory");
        }
        if (tid < 192) {                            // tail: idx = 6144 + tid
            int idx = 6144 + tid;
            int c   = idx / 396;
            int rem = idx - c * 396;
            int r   = rem / 66;
            int col = rem - r * 66;
            int y  = r0 - 1 + r;
            int xx = col - 1;
            float v = 0.f;
            if ((unsigned)y < 64u && (unsigned)xx < 64u)
                v = x[(((b * 16 + c) << 6) + y) * 64 + xx];
            uint32_t hw0, lw0, hw1, lw1;
            phi_quant(v, hw0, lw0, hw1, lw1);
            uint32_t a = sb + c * PHI_C8 + r * PHI_R8 + col * 16;
            asm volatile("st.shared.v4.b32 [%0], {%1,%2,%3,%4};"
                         :: "r"(a), "r"(hw0), "r"(lw0), "r"(hw1), "r"(lw1) : "memory");
        }
    }
    // schedule table: [wh][m in 0..36): chunk kc = wh*18 + (m mod 18)
    // entry = 4 words {off(d0), off(d2), off(d1), off(d3)}, d_i = 4kc+i
    if (tid < 72) {
        int whh = (tid >= 36);
        int m   = tid - whh * 36;
        int cj  = m - (m >= 18 ? 18 : 0);
        int kc  = whh * 18 + cj;
        uint32_t o4[4];
#pragma unroll
        for (int i = 0; i < 4; ++i) {
            int d = 4 * kc + i;
            int c = d / 9, r9 = d - 9 * c;
            o4[i] = (uint32_t)(c * PHI_C8 + (r9 / 3) * PHI_R8 + (r9 % 3) * 16);
        }
        uint32_t a = sb + OFF_TAB8 + tid * 16;
        asm volatile("st.shared.v4.b32 [%0], {%1,%2,%3,%4};"
                     :: "r"(a), "r"(o4[0]), "r"(o4[2]), "r"(o4[1]), "r"(o4[3]) : "memory");
    }
    asm volatile("cp.async.wait_group 0;" ::: "memory");
    __syncthreads();

    // ---------------- s8 mma mainloop (k-split, staggered) -----------------
    const int lane = tid & 31;
    const int w    = tid >> 5;
    const int wh   = w >> 3;                 // k-half
    const int wp   = w & 7;                  // pixel-tile warp id
    const int prow = wp >> 1;
    const int pc   = (wp & 1) << 5;
    const int qr   = lane >> 2;
    const int gp   = lane & 3;
    const int start = wp * 2 + wh;           // 0..15, SMSP-mates desynced

    const uint32_t abase = sb + (uint32_t)prow * PHI_R8
                         + (uint32_t)(pc + qr) * 16 + (uint32_t)(gp & 1) * 8;
    const uint32_t tb    = sb + OFF_TAB8 + (uint32_t)wh * 576
                         + (uint32_t)start * 16 + (uint32_t)(gp >> 1) * 8;
    const uint32_t swB   = sb + SM_W + (uint32_t)wh * 36864 + (uint32_t)lane * 16;

    int acch[2][4][4], accm[2][4][4];
#pragma unroll
    for (int t = 0; t < 2; ++t)
#pragma unroll
        for (int n = 0; n < 4; ++n)
#pragma unroll
            for (int r = 0; r < 4; ++r) { acch[t][n][r] = 0; accm[t][n][r] = 0; }

    uint32_t Eax, Eay;
    lds64(tb, Eax, Eay);
    int cjr = start;

#pragma unroll 3
    for (int j = 0; j < 18; ++j) {
        // ---- A fragments (h+l pairs), 8 x LDS.64 ----
        uint32_t Ah0[4], Al0[4], Ah1[4], Al1[4];
        {
            uint32_t aA = abase + Eax, aB = abase + Eay;
            lds64(aA,        Ah0[0], Al0[0]);
            lds64(aA + 128,  Ah0[1], Al0[1]);
            lds64(aB,        Ah0[2], Al0[2]);
            lds64(aB + 128,  Ah0[3], Al0[3]);
            lds64(aA + 256,  Ah1[0], Al1[0]);
            lds64(aA + 384,  Ah1[1], Al1[1]);
            lds64(aB + 256,  Ah1[2], Al1[2]);
            lds64(aB + 384,  Ah1[3], Al1[3]);
        }
        // ---- B fragments from smem, 4 x LDS.128 ----
        uint32_t bbase = swB + (uint32_t)cjr * 2048;
        uint4 Bb[4];
#pragma unroll
        for (int nl = 0; nl < 4; ++nl) Bb[nl] = lds128(bbase + nl * 512);

        // table prefetch for next iteration
        lds64(tb + (j + 1) * 16, Eax, Eay);

        // ---- 24 mma: HH -> acc_hi ; LH + HL -> acc_mid ----
#pragma unroll
        for (int nl = 0; nl < 4; ++nl) {
            mmai(acch[0][nl], Ah0, Bb[nl].x, Bb[nl].y);
            mmai(acch[1][nl], Ah1, Bb[nl].x, Bb[nl].y);
        }
#pragma unroll
        for (int nl = 0; nl < 4; ++nl) {
            mmai(accm[0][nl], Al0, Bb[nl].x, Bb[nl].y);
            mmai(accm[1][nl], Al1, Bb[nl].x, Bb[nl].y);
        }
#pragma unroll
        for (int nl = 0; nl < 4; ++nl) {
            mmai(accm[0][nl], Ah0, Bb[nl].z, Bb[nl].w);
            mmai(accm[1][nl], Ah1, Bb[nl].z, Bb[nl].w);
        }

        cjr = (cjr == 17) ? 0 : cjr + 1;
    }

    // ---------------- Merge k-halves exactly (int) through dead Phi smem ---
    __syncthreads();
    if (wh == 1) {
        uint32_t mb = sb + (uint32_t)wp * 8192 + (uint32_t)lane * 16;
#pragma unroll
        for (int t = 0; t < 2; ++t)
#pragma unroll
            for (int nl = 0; nl < 4; ++nl) {
                uint32_t a = mb + (uint32_t)(t * 4 + nl) * 512;
                asm volatile("st.shared.v4.b32 [%0], {%1,%2,%3,%4};"
                             :: "r"(a), "r"(acch[t][nl][0]), "r"(acch[t][nl][1]),
                                "r"(acch[t][nl][2]), "r"(acch[t][nl][3]) : "memory");
                asm volatile("st.shared.v4.b32 [%0], {%1,%2,%3,%4};"
                             :: "r"(a + 4096), "r"(accm[t][nl][0]), "r"(accm[t][nl][1]),
                                "r"(accm[t][nl][2]), "r"(accm[t][nl][3]) : "memory");
            }
    }
    __syncthreads();

    float cf[2][4][4];
    if (wh == 0) {
        uint32_t mb = sb + (uint32_t)wp * 8192 + (uint32_t)lane * 16;
#pragma unroll
        for (int t = 0; t < 2; ++t)
#pragma unroll
            for (int nl = 0; nl < 4; ++nl) {
                uint32_t a = mb + (uint32_t)(t * 4 + nl) * 512;
                int h0, h1, h2, h3, m0, m1, m2, m3;
                asm("ld.shared.v4.b32 {%0,%1,%2,%3}, [%4];"
                    : "=r"(h0), "=r"(h1), "=r"(h2), "=r"(h3) : "r"(a));
                asm("ld.shared.v4.b32 {%0,%1,%2,%3}, [%4];"
                    : "=r"(m0), "=r"(m1), "=r"(m2), "=r"(m3) : "r"(a + 4096));
                int H0 = acch[t][nl][0] + h0, M0 = accm[t][nl][0] + m0;
                int H1 = acch[t][nl][1] + h1, M1 = accm[t][nl][1] + m1;
                int H2 = acch[t][nl][2] + h2, M2 = accm[t][nl][2] + m2;
                int H3 = acch[t][nl][3] + h3, M3 = accm[t][nl][3] + m3;
                float s0 = ssc[nl * 8 + (gp << 1)];
                float s1 = ssc[nl * 8 + (gp << 1) + 1];
                const float i256 = 0.00390625f;
                cf[t][nl][0] = s0 * fmaf((float)M0, i256, (float)H0);
                cf[t][nl][1] = s1 * fmaf((float)M1, i256, (float)H1);
                cf[t][nl][2] = s0 * fmaf((float)M2, i256, (float)H2);
                cf[t][nl][3] = s1 * fmaf((float)M3, i256, (float)H3);
            }
    }

    // ---------------- per-o partial stats (wh==0 warps) --------------------
    if (wh == 0) {
        float S[4][2], Q[4][2];
#pragma unroll
        for (int nl = 0; nl < 4; ++nl)
#pragma unroll
            for (int h = 0; h < 2; ++h) {
                float v0 = cf[0][nl][h],     v1 = cf[0][nl][h + 2];
                float v2 = cf[1][nl][h],     v3 = cf[1][nl][h + 2];
                S[nl][h] = (v0 + v1) + (v2 + v3);
                float q = __fmul_rn(v0, v0);
                q = fmaf(v1, v1, q); q = fmaf(v2, v2, q); q = fmaf(v3, v3, q);
                Q[nl][h] = q;
            }
#pragma unroll
        for (int off = 4; off <= 16; off <<= 1)
#pragma unroll
            for (int nl = 0; nl < 4; ++nl)
#pragma unroll
                for (int h = 0; h < 2; ++h) {
                    S[nl][h] += __shfl_xor_sync(0xFFFFFFFFu, S[nl][h], off);
                    Q[nl][h] += __shfl_xor_sync(0xFFFFFFFFu, Q[nl][h], off);
                }
        if (qr == 0) {
#pragma unroll
            for (int nl = 0; nl < 4; ++nl)
#pragma unroll
                for (int h = 0; h < 2; ++h) {
                    sred[wp][nl][h][0][gp] = S[nl][h];
                    sred[wp][nl][h][1][gp] = Q[nl][h];
                }
        }
    }
    __syncthreads();
    if (tid < 32) {
        int o = tid;
        int nt = o >> 3, rem = o & 7, gpp = rem >> 1, h = rem & 1;
        float Ss = 0.f, Qq = 0.f;
#pragma unroll
        for (int ww = 0; ww < 8; ++ww) {
            Ss += sred[ww][nt][h][0][gpp];
            Qq += sred[ww][nt][h][1][gpp];
        }
        g_part[o * 128 + cta] = make_float2(Ss, Qq);
    }

    grid_barrier(&g_barC);

    // ---------------- BN params (deterministic) + apply + store ------------
    if (tid < 256) {
        int o = tid >> 3, jj = tid & 7;
        float Ss = 0.f, Qq = 0.f;
#pragma unroll
        for (int i = 0; i < 16; ++i) {
            float2 pq = g_part[o * 128 + jj * 16 + i];
            Ss += pq.x; Qq += pq.y;
        }
#pragma unroll
        for (int off = 1; off <= 4; off <<= 1) {
            Ss += __shfl_xor_sync(0xFFFFFFFFu, Ss, off);
            Qq += __shfl_xor_sync(0xFFFFFFFFu, Qq, off);
        }
        if (jj == 0) {
            float mean = Ss * (1.f / 32768.f);
            float var  = Qq * (1.f / 32768.f) - mean * mean;
            float sc = gamma[o] * rsqrtf(var + 1e-5f);
            bnp[o] = make_float2(sc, fmaf(-mean, sc, beta[o]));
        }
    }
    __syncthreads();

    if (wh == 0) {
        float* ob = out + ((size_t)b << 17) + (size_t)(r0 + prow) * 64;
#pragma unroll
        for (int t = 0; t < 2; ++t) {
            int col0 = pc + (t << 4) + qr;
#pragma unroll
            for (int nl = 0; nl < 4; ++nl) {
                int o0 = nl * 8 + (gp << 1);
                float2 n0 = bnp[o0];
                float2 n1 = bnp[o0 + 1];
                float* p0 = ob + ((size_t)o0 << 12);
                p0[col0]            = fmaf(cf[t][nl][0], n0.x, n0.y);
                p0[4096 + col0]     = fmaf(cf[t][nl][1], n1.x, n1.y);
                p0[col0 + 8]        = fmaf(cf[t][nl][2], n0.x, n0.y);
                p0[4096 + col0 + 8] = fmaf(cf[t][nl][3], n1.x, n1.y);
            }
        }
    }
}

// ---------------------------------------------------------------------------
extern "C" void kernel_launch(void* const* d_in, const int* in_sizes, int n_in,
                              void* d_out, int out_size) {
    const float* x     = (const float*)d_in[0];
    const float* W     = (const float*)d_in[1];
    const float* gamma = (const float*)d_in[2];
    const float* beta  = (const float*)d_in[3];
    float* out = (float*)d_out;

    cudaFuncSetAttribute(kan_fused, cudaFuncAttributeMaxDynamicSharedMemorySize, SMEM_TOT);

    wsum_part<<<512, 288>>>(W);
    wsum_comb<<<128, 288>>>();
    quant_pack<<<128, 288>>>();
    kan_fused <<<128, 512, SMEM_TOT>>>(x, gamma, beta, out);
}